// round 14
// baseline (speedup 1.0000x reference)
#include <cuda_runtime.h>

// SIR recurrence, round 13: R12's 3-chain / 6-cyc-floor body + de-noised loop.
//     r' = fma(-(1-K), w, r)
//     w' = fma(g, w, A*B)          <- stored; s0 = w * (1/A)
//     g' = fma(-w, g, r')
// FMA pipe is saturated at the 6-cyc floor (3 FFMA x rt 2), so the loop is
// restructured to keep everything else out of the way:
//   - 4 w-values buffered in registers -> one STS.128 per 4 iters
//   - 4-step straight-line groups x unroll 8 = 32 steps per branch
//
// Producer/consumer pipeline (proven): warps 1..7 scale w->s0, reconstruct
// s1/s3 (prefix of s0) and s2 (telescoped), overlapped per 672-step chunk.

#define CH        672            // 224 consumer threads * 3 rows; 672 % 4 == 0
#define NCH       4              // ceil(2047 / 672)
#define MAX_STEPS 2048

#define NB_ARRIVE(id, cnt) \
    asm volatile("bar.arrive %0, %1;" :: "r"(id), "r"(cnt) : "memory")
#define NB_SYNC(id, cnt) \
    asm volatile("bar.sync %0, %1;" :: "r"(id), "r"(cnt) : "memory")

__global__ void __launch_bounds__(256, 1)
sir_kernel(const float* __restrict__ x,
           const float* __restrict__ w2p,
           const float* __restrict__ w3p,
           const float* __restrict__ b3p,
           const float* __restrict__ w4p,
           float* __restrict__ out,
           int n)
{
    __shared__ __align__(16) float s0buf[MAX_STEPS];  // w_i = A*s0_i (or s0_i)
    __shared__ float wpart[8];

    const int tid   = threadIdx.x;
    const int steps = n - 1;            // 2047

    const float w2 = *w2p, w3 = *w3p, b3 = *b3p, w4 = *w4p;
    const float w2sq = w2 * w2;
    const float w4sq = w4 * w4;
    const float K    = 1.0f - w2sq - w4sq;
    const float oneK = w2sq + w4sq;     // 1 - K
    const float A    = w3 * w3 * 1.0e-3f;
    const float B    = fmaf(w3, b3, b3);
    const bool  wmode = fabsf(A) > 1e-20f;          // uniform across block
    const float scale = wmode ? (1.0f / A) : 1.0f;  // s0 = buf * scale

    if (tid < 32) {
        // ---------------- producer: warp 0 (convergent barriers) ----------------
        const float h0 = fmaf(A, x[0] + x[2], K);   // K + A*u0
        float w = A * x[0];
        float g = h0 - w;
        float r = h0 - A * B;
        const float AB  = A * B;
        const float nK1 = -oneK;

        // fallback state (R11 body, for |A| ~ 0)
        float s0f = x[0];
        float hf  = h0;
        const float negA = -A;
        const float negE = -(A * oneK);

        int done = 0;
        for (int c = 0; c < NCH; ++c) {
            const int end = (done + CH < steps) ? done + CH : steps;
            if (tid == 0) {
                if (wmode) {
                    // vectorized main body: groups of 4 steps, STS.128 each
                    const int nfull = (end - done) & ~3;
                    const int end4  = done + nfull;
                    float4* v = reinterpret_cast<float4*>(s0buf + done);
                    #pragma unroll 8
                    for (int i = done; i < end4; i += 4, ++v) {
                        float4 buf4;
                        float rn, gn;
                        // step 1
                        rn = fmaf(nK1, w, r);
                        buf4.x = fmaf(g, w, AB);
                        gn = fmaf(-w, g, rn);
                        r = rn; w = buf4.x; g = gn;
                        // step 2
                        rn = fmaf(nK1, w, r);
                        buf4.y = fmaf(g, w, AB);
                        gn = fmaf(-w, g, rn);
                        r = rn; w = buf4.y; g = gn;
                        // step 3
                        rn = fmaf(nK1, w, r);
                        buf4.z = fmaf(g, w, AB);
                        gn = fmaf(-w, g, rn);
                        r = rn; w = buf4.z; g = gn;
                        // step 4
                        rn = fmaf(nK1, w, r);
                        buf4.w = fmaf(g, w, AB);
                        gn = fmaf(-w, g, rn);
                        r = rn; w = buf4.w; g = gn;

                        *v = buf4;                  // one STS.128 / 4 steps
                    }
                    // scalar tail (last chunk: 2047 % 4 = 3... handled here)
                    for (int i = end4; i < end; ++i) {
                        const float rn2 = fmaf(nK1, w, r);
                        const float wn2 = fmaf(g,  w, AB);
                        const float gn2 = fmaf(-w, g, rn2);
                        s0buf[i] = wn2;
                        r = rn2; w = wn2; g = gn2;
                    }
                } else {
                    #pragma unroll 16
                    for (int i = done; i < end; ++i) {
                        const float gg = fmaf(negA, s0f, hf);
                        const float t  = fmaf(s0f, gg, B);
                        hf  = fmaf(negE, s0f, hf);
                        s0f = t;
                        s0buf[i] = s0f;
                    }
                }
            }
            done = end;
            __syncwarp();
            NB_ARRIVE(c + 1, 256);       // whole warp arrives, convergently
        }
    } else {
        // ---------------- consumers: warps 1..7 (224 threads) ----------------
        const int      ctid = tid - 32;          // 0..223
        const int      cw   = ctid >> 5;         // consumer warp 0..6
        const unsigned lane = tid & 31u;

        const float x0 = x[0], x1 = x[1], x3 = x[3];
        const float base2 = x[2] + K * x0;       // x2 + K*x0
        const float noneK = -oneK;

        float carry = 0.0f;

        for (int c = 0; c < NCH; ++c) {
            NB_SYNC(c + 1, 256);                 // wait for producer chunk c

            const int r0 = c * CH + ctid * 3;
            float v0 = (r0     < steps) ? s0buf[r0]     * scale : 0.0f;
            float v1 = (r0 + 1 < steps) ? s0buf[r0 + 1] * scale : 0.0f;
            float v2 = (r0 + 2 < steps) ? s0buf[r0 + 2] * scale : 0.0f;

            const float l1  = v0 + v1;
            const float run = l1 + v2;

            float scan = run;
            #pragma unroll
            for (int off = 1; off < 32; off <<= 1) {
                const float o = __shfl_up_sync(0xffffffffu, scan, off);
                if (lane >= off) scan += o;
            }
            if (lane == 31) wpart[cw] = scan;
            NB_SYNC(15, 224);                    // consumer-internal, convergent

            float woff = 0.0f, chtot = 0.0f;
            #pragma unroll
            for (int w = 0; w < 7; ++w) {
                const float pv = wpart[w];
                chtot += pv;
                if (w < cw) woff += pv;
            }

            float Qexc = carry + woff + (scan - run);

            #pragma unroll
            for (int k = 0; k < 3; ++k) {
                const int r = r0 + k;
                const float s0v = (k == 0) ? v0 : (k == 1) ? v1 : v2;
                if (r < steps) {
                    const float S = x0 + Qexc;
                    float* o = out + 5 * r;
                    o[0] = s0v;
                    o[1] = fmaf(w2sq, S, x1);
                    o[2] = fmaf(noneK, Qexc, base2 - s0v);
                    o[3] = fmaf(w4sq, S, x3);
                    o[4] = 0.0f;
                }
                Qexc += s0v;
            }

            carry += chtot;
        }
    }
}

extern "C" void kernel_launch(void* const* d_in, const int* in_sizes, int n_in,
                              void* d_out, int out_size)
{
    const float* x  = (const float*)d_in[0];
    const float* w2 = (const float*)d_in[1];
    const float* w3 = (const float*)d_in[2];
    const float* b3 = (const float*)d_in[3];
    const float* w4 = (const float*)d_in[4];
    float* out = (float*)d_out;

    const int n = out_size / 5 + 1;   // out_size = (n-1)*5

    sir_kernel<<<1, 256>>>(x, w2, w3, b3, w4, out, n);
}

// round 15
// speedup vs baseline: 1.2429x; 1.2429x over previous
#include <cuda_runtime.h>

// SIR recurrence, round 14: 3-chain / 6-cyc-floor body, 48-step bodies.
//     r' = fma(-(1-K), w, r)
//     w' = fma(g, w, A*B)          <- stored; s0 = w * (1/A)
//     g' = fma(-w, g, r')
// FMA pipe saturated at 6 cyc/step (3 FFMA x rt 2). Overhead minimized:
//   - 4-step groups, one STS.128 each, immediate offsets
//   - 12 groups (48 steps) per branch; 672/4 = 168 = 12*14 exact
//
// Producer/consumer pipeline (proven): warps 1..7 scale w->s0, reconstruct
// s1/s3 (prefix of s0) and s2 (telescoped), overlapped per 672-step chunk.

#define CH        672            // 224 consumer threads * 3 rows; 672 % 48 == 0
#define NCH       4              // ceil(2047 / 672)
#define MAX_STEPS 2048

#define NB_ARRIVE(id, cnt) \
    asm volatile("bar.arrive %0, %1;" :: "r"(id), "r"(cnt) : "memory")
#define NB_SYNC(id, cnt) \
    asm volatile("bar.sync %0, %1;" :: "r"(id), "r"(cnt) : "memory")

// one 4-step group: advances (r, w, g) by 4 and stores 4 w's as float4
#define STEP(dst)  do {                         \
        const float rn = fmaf(nK1, w, r);       \
        const float wn = fmaf(g,   w, AB);      \
        const float gn = fmaf(-w,  g, rn);      \
        (dst) = wn;                             \
        r = rn; w = wn; g = gn;                 \
    } while (0)

#define GROUP4(v, j)  do {                      \
        float4 b4;                              \
        STEP(b4.x); STEP(b4.y);                 \
        STEP(b4.z); STEP(b4.w);                 \
        (v)[j] = b4;                            \
    } while (0)

__global__ void __launch_bounds__(256, 1)
sir_kernel(const float* __restrict__ x,
           const float* __restrict__ w2p,
           const float* __restrict__ w3p,
           const float* __restrict__ b3p,
           const float* __restrict__ w4p,
           float* __restrict__ out,
           int n)
{
    __shared__ __align__(16) float s0buf[MAX_STEPS];  // w_i = A*s0_i (or s0_i)
    __shared__ float wpart[8];

    const int tid   = threadIdx.x;
    const int steps = n - 1;            // 2047

    const float w2 = *w2p, w3 = *w3p, b3 = *b3p, w4 = *w4p;
    const float w2sq = w2 * w2;
    const float w4sq = w4 * w4;
    const float K    = 1.0f - w2sq - w4sq;
    const float oneK = w2sq + w4sq;     // 1 - K
    const float A    = w3 * w3 * 1.0e-3f;
    const float B    = fmaf(w3, b3, b3);
    const bool  wmode = fabsf(A) > 1e-20f;          // uniform across block
    const float scale = wmode ? (1.0f / A) : 1.0f;  // s0 = buf * scale

    if (tid < 32) {
        // ---------------- producer: warp 0 (convergent barriers) ----------------
        const float h0 = fmaf(A, x[0] + x[2], K);   // K + A*u0
        float w = A * x[0];
        float g = h0 - w;
        float r = h0 - A * B;
        const float AB  = A * B;
        const float nK1 = -oneK;

        // fallback state (R11 body, for |A| ~ 0)
        float s0f = x[0];
        float hf  = h0;
        const float negA = -A;
        const float negE = -(A * oneK);

        int done = 0;
        for (int c = 0; c < NCH; ++c) {
            const int end = (done + CH < steps) ? done + CH : steps;
            if (tid == 0) {
                if (wmode) {
                    const int ngrp  = (end - done) >> 2;       // full 4-groups
                    const int nbody = ngrp / 12;               // 48-step bodies
                    float4* v = reinterpret_cast<float4*>(s0buf + done);
                    for (int b = 0; b < nbody; ++b, v += 12) {
                        GROUP4(v, 0);  GROUP4(v, 1);  GROUP4(v, 2);
                        GROUP4(v, 3);  GROUP4(v, 4);  GROUP4(v, 5);
                        GROUP4(v, 6);  GROUP4(v, 7);  GROUP4(v, 8);
                        GROUP4(v, 9);  GROUP4(v, 10); GROUP4(v, 11);
                    }
                    // leftover groups + scalar tail (only in the short last chunk)
                    int i = done + nbody * 48;
                    for (; i + 4 <= end; i += 4) {
                        float4 b4;
                        STEP(b4.x); STEP(b4.y); STEP(b4.z); STEP(b4.w);
                        *reinterpret_cast<float4*>(s0buf + i) = b4;
                    }
                    for (; i < end; ++i) {
                        const float rn = fmaf(nK1, w, r);
                        const float wn = fmaf(g,  w, AB);
                        const float gn = fmaf(-w, g, rn);
                        s0buf[i] = wn;
                        r = rn; w = wn; g = gn;
                    }
                } else {
                    #pragma unroll 16
                    for (int i = done; i < end; ++i) {
                        const float gg = fmaf(negA, s0f, hf);
                        const float t  = fmaf(s0f, gg, B);
                        hf  = fmaf(negE, s0f, hf);
                        s0f = t;
                        s0buf[i] = s0f;
                    }
                }
            }
            done = end;
            __syncwarp();
            NB_ARRIVE(c + 1, 256);       // whole warp arrives, convergently
        }
    } else {
        // ---------------- consumers: warps 1..7 (224 threads) ----------------
        const int      ctid = tid - 32;          // 0..223
        const int      cw   = ctid >> 5;         // consumer warp 0..6
        const unsigned lane = tid & 31u;

        const float x0 = x[0], x1 = x[1], x3 = x[3];
        const float base2 = x[2] + K * x0;       // x2 + K*x0
        const float noneK = -oneK;

        float carry = 0.0f;

        for (int c = 0; c < NCH; ++c) {
            NB_SYNC(c + 1, 256);                 // wait for producer chunk c

            const int r0 = c * CH + ctid * 3;
            float v0 = (r0     < steps) ? s0buf[r0]     * scale : 0.0f;
            float v1 = (r0 + 1 < steps) ? s0buf[r0 + 1] * scale : 0.0f;
            float v2 = (r0 + 2 < steps) ? s0buf[r0 + 2] * scale : 0.0f;

            const float l1  = v0 + v1;
            const float run = l1 + v2;

            float scan = run;
            #pragma unroll
            for (int off = 1; off < 32; off <<= 1) {
                const float o = __shfl_up_sync(0xffffffffu, scan, off);
                if (lane >= off) scan += o;
            }
            if (lane == 31) wpart[cw] = scan;
            NB_SYNC(15, 224);                    // consumer-internal, convergent

            float woff = 0.0f, chtot = 0.0f;
            #pragma unroll
            for (int w = 0; w < 7; ++w) {
                const float pv = wpart[w];
                chtot += pv;
                if (w < cw) woff += pv;
            }

            float Qexc = carry + woff + (scan - run);

            #pragma unroll
            for (int k = 0; k < 3; ++k) {
                const int r = r0 + k;
                const float s0v = (k == 0) ? v0 : (k == 1) ? v1 : v2;
                if (r < steps) {
                    const float S = x0 + Qexc;
                    float* o = out + 5 * r;
                    o[0] = s0v;
                    o[1] = fmaf(w2sq, S, x1);
                    o[2] = fmaf(noneK, Qexc, base2 - s0v);
                    o[3] = fmaf(w4sq, S, x3);
                    o[4] = 0.0f;
                }
                Qexc += s0v;
            }

            carry += chtot;
        }
    }
}

extern "C" void kernel_launch(void* const* d_in, const int* in_sizes, int n_in,
                              void* d_out, int out_size)
{
    const float* x  = (const float*)d_in[0];
    const float* w2 = (const float*)d_in[1];
    const float* w3 = (const float*)d_in[2];
    const float* b3 = (const float*)d_in[3];
    const float* w4 = (const float*)d_in[4];
    float* out = (float*)d_out;

    const int n = out_size / 5 + 1;   // out_size = (n-1)*5

    sir_kernel<<<1, 256>>>(x, w2, w3, b3, w4, out, n);
}